// round 2
// baseline (speedup 1.0000x reference)
#include <cuda_runtime.h>

#define Dm 16
#define Hh 8
#define Ll 8
#define Kk 35
#define Sq 101
#define RS 20          // padded row stride (floats) for q/k/v rows in smem
#define BLOCK 128

// shared-weight buffer offsets (floats)
#define OWQKV 0        // 768
#define OBQKV 768      // 48
#define OWO   816      // 256
#define OBO   1072     // 16
#define OW1   1088     // 256
#define OB1   1344     // 16
#define OW2   1360     // 256
#define OB2   1616     // 16
#define OG1   1632
#define OBE1  1648
#define OG2   1664
#define OBE2  1680
#define WTOT  1696

__device__ __forceinline__ float dot16(const float* v, const float4* w4) {
    float acc = 0.f;
    #pragma unroll
    for (int j = 0; j < 4; j++) {
        float4 w = w4[j];
        acc += v[4*j+0]*w.x + v[4*j+1]*w.y + v[4*j+2]*w.z + v[4*j+3]*w.w;
    }
    return acc;
}

__device__ __forceinline__ void layernorm16(const float* in, const float* g,
                                            const float* bia, float* out) {
    float mu = 0.f;
    #pragma unroll
    for (int d = 0; d < 16; d++) mu += in[d];
    mu *= (1.f/16.f);
    float var = 0.f;
    #pragma unroll
    for (int d = 0; d < 16; d++) { float c = in[d] - mu; var += c*c; }
    var *= (1.f/16.f);
    float inv = rsqrtf(var + 1e-5f);
    #pragma unroll
    for (int d = 0; d < 16; d++) out[d] = (in[d] - mu) * inv * g[d] + bia[d];
}

__global__ __launch_bounds__(BLOCK) void TorrinE0_kernel(
    const float* __restrict__ x,
    const float* __restrict__ conv_w,
    const float* __restrict__ conv_b,
    const float* __restrict__ cls_emb,
    const float* __restrict__ Wqkv,
    const float* __restrict__ bqkv,
    const float* __restrict__ Wo,
    const float* __restrict__ bo,
    const float* __restrict__ W1,
    const float* __restrict__ b1,
    const float* __restrict__ W2,
    const float* __restrict__ b2,
    const float* __restrict__ ln1_g, const float* __restrict__ ln1_b,
    const float* __restrict__ ln2_g, const float* __restrict__ ln2_b,
    const float* __restrict__ lnf_g, const float* __restrict__ lnf_b,
    const float* __restrict__ end_w, const float* __restrict__ end_b,
    const float* __restrict__ head_w, const float* __restrict__ head_b,
    float* __restrict__ out)
{
    // q rows [0 .. Sq*RS), k rows [Sq*RS .. 2*Sq*RS), v rows [2*Sq*RS .. 3*Sq*RS)
    // also aliased as x-row staging (3500 floats <= 6060) before the layer loop.
    __shared__ __align__(16) float sqkv[3 * Sq * RS];
    __shared__ __align__(16) float sw[WTOT];
    __shared__ float sred[4];
    __shared__ float scls[16];

    const int b   = blockIdx.x;
    const int tid = threadIdx.x;

    // ---- stage x row + conv weights into smem ----
    const float* xr = x + (size_t)b * 3500;
    for (int i = tid; i < 3500; i += BLOCK) sqkv[i] = xr[i];
    for (int i = tid; i < 560; i += BLOCK) sw[i] = conv_w[i];
    if (tid < 16) sw[560 + tid] = conv_b[tid];
    __syncthreads();

    // ---- conv patchify -> per-token h in registers ----
    float h[16];
    if (tid == 0) {
        #pragma unroll
        for (int d = 0; d < 16; d++) h[d] = cls_emb[d];
    } else if (tid <= 100) {
        const float* ps = &sqkv[(tid - 1) * Kk];
        #pragma unroll
        for (int f = 0; f < 16; f++) {
            float acc = sw[560 + f];
            for (int k = 0; k < Kk; k++) acc += ps[k] * sw[f * Kk + k];
            h[f] = acc;
        }
    }
    __syncthreads();   // conv reads of sqkv/sw done before overwrite

    const float scale = 0.70710678118654752f;   // 1/sqrt(D/H) = 1/sqrt(2)

    #pragma unroll 1
    for (int l = 0; l < Ll; l++) {
        // ---- stage layer weights ----
        for (int i = tid; i < 768; i += BLOCK) sw[OWQKV + i] = Wqkv[l*768 + i];
        if (tid < 48) sw[OBQKV + tid] = bqkv[l*48 + tid];
        for (int i = tid; i < 256; i += BLOCK) {
            sw[OWO + i] = Wo[l*256 + i];
            sw[OW1 + i] = W1[l*256 + i];
            sw[OW2 + i] = W2[l*256 + i];
        }
        if (tid < 16) {
            sw[OBO  + tid] = bo[l*16 + tid];
            sw[OB1  + tid] = b1[l*16 + tid];
            sw[OB2  + tid] = b2[l*16 + tid];
            sw[OG1  + tid] = ln1_g[l*16 + tid];
            sw[OBE1 + tid] = ln1_b[l*16 + tid];
            sw[OG2  + tid] = ln2_g[l*16 + tid];
            sw[OBE2 + tid] = ln2_b[l*16 + tid];
        }
        __syncthreads();

        // ---- fused qkv projection -> smem rows (q pre-scaled) ----
        if (tid <= 100) {
            float* qrow = &sqkv[tid * RS];
            float* krow = &sqkv[Sq * RS + tid * RS];
            float* vrow = &sqkv[2 * Sq * RS + tid * RS];
            const float4* wq4 = (const float4*)&sw[OWQKV];
            for (int e = 0; e < 16; e++) {
                float a0 = sw[OBQKV + e]      + dot16(h, wq4 + e * 4);
                float a1 = sw[OBQKV + 16 + e] + dot16(h, wq4 + (16 + e) * 4);
                float a2 = sw[OBQKV + 32 + e] + dot16(h, wq4 + (32 + e) * 4);
                qrow[e] = a0 * scale;
                krow[e] = a1;
                vrow[e] = a2;
            }
        }
        __syncthreads();

        // ---- attention + out-proj + LN1 + FFN + LN2 (all per-token) ----
        if (tid <= 100) {
            float qr[16];
            {
                const float4* q4 = (const float4*)&sqkv[tid * RS];
                #pragma unroll
                for (int j = 0; j < 4; j++) {
                    float4 t0 = q4[j];
                    qr[4*j] = t0.x; qr[4*j+1] = t0.y; qr[4*j+2] = t0.z; qr[4*j+3] = t0.w;
                }
            }
            float ctx[16], ssum[8];
            #pragma unroll
            for (int d = 0; d < 16; d++) ctx[d] = 0.f;
            #pragma unroll
            for (int i = 0; i < 8; i++) ssum[i] = 0.f;

            const float4* kb = (const float4*)&sqkv[Sq * RS];
            const float4* vb = (const float4*)&sqkv[2 * Sq * RS];
            for (int t = 0; t < Sq; t++) {
                float kk[16], vv[16];
                #pragma unroll
                for (int j = 0; j < 4; j++) {
                    float4 kv = kb[t * 5 + j];
                    kk[4*j] = kv.x; kk[4*j+1] = kv.y; kk[4*j+2] = kv.z; kk[4*j+3] = kv.w;
                    float4 vf = vb[t * 5 + j];
                    vv[4*j] = vf.x; vv[4*j+1] = vf.y; vv[4*j+2] = vf.z; vv[4*j+3] = vf.w;
                }
                #pragma unroll
                for (int hh = 0; hh < 8; hh++) {
                    float sc = qr[2*hh] * kk[2*hh] + qr[2*hh+1] * kk[2*hh+1];
                    float e  = __expf(sc);
                    ssum[hh] += e;
                    ctx[2*hh]   += e * vv[2*hh];
                    ctx[2*hh+1] += e * vv[2*hh+1];
                }
            }
            #pragma unroll
            for (int hh = 0; hh < 8; hh++) {
                float r = __fdividef(1.f, ssum[hh]);
                ctx[2*hh]   *= r;
                ctx[2*hh+1] *= r;
            }

            // out projection + residual
            float nh[16];
            const float4* wo4 = (const float4*)&sw[OWO];
            #pragma unroll
            for (int o = 0; o < 16; o++)
                nh[o] = h[o] + sw[OBO + o] + dot16(ctx, wo4 + o * 4);
            layernorm16(nh, &sw[OG1], &sw[OBE1], h);

            // FFN
            float ff[16];
            const float4* w14 = (const float4*)&sw[OW1];
            #pragma unroll
            for (int f = 0; f < 16; f++)
                ff[f] = fmaxf(sw[OB1 + f] + dot16(h, w14 + f * 4), 0.f);
            const float4* w24 = (const float4*)&sw[OW2];
            #pragma unroll
            for (int d = 0; d < 16; d++)
                nh[d] = h[d] + sw[OB2 + d] + dot16(ff, w24 + d * 4);
            layernorm16(nh, &sw[OG2], &sw[OBE2], h);
        }
        __syncthreads();   // all reads of sqkv done before next layer overwrites
    }

    // ---- final LN on CLS row + classification head ----
    if (tid == 0) {
        float mu = 0.f;
        #pragma unroll
        for (int d = 0; d < 16; d++) mu += h[d];
        mu *= (1.f/16.f);
        float var = 0.f;
        #pragma unroll
        for (int d = 0; d < 16; d++) { float c = h[d] - mu; var += c*c; }
        var *= (1.f/16.f);
        float inv = rsqrtf(var + 1e-5f);
        #pragma unroll
        for (int d = 0; d < 16; d++)
            scls[d] = (h[d] - mu) * inv * lnf_g[d] + lnf_b[d];
    }
    __syncthreads();

    float part = 0.f;
    if (tid < 100) {
        const float4* ew = (const float4*)(end_w + tid * 16);
        float acc = end_b[tid] + dot16(scls, ew);
        part = acc * head_w[tid];
    }
    #pragma unroll
    for (int off = 16; off > 0; off >>= 1)
        part += __shfl_down_sync(0xffffffffu, part, off);
    if ((tid & 31) == 0) sred[tid >> 5] = part;
    __syncthreads();
    if (tid == 0) {
        float z = sred[0] + sred[1] + sred[2] + sred[3] + head_b[0];
        out[b] = 1.f / (1.f + __expf(-z));
    }
}

extern "C" void kernel_launch(void* const* d_in, const int* in_sizes, int n_in,
                              void* d_out, int out_size) {
    const float* x      = (const float*)d_in[0];
    const float* conv_w = (const float*)d_in[1];
    const float* conv_b = (const float*)d_in[2];
    const float* cls_e  = (const float*)d_in[3];
    const float* Wqkv   = (const float*)d_in[4];
    const float* bqkv   = (const float*)d_in[5];
    const float* Wo     = (const float*)d_in[6];
    const float* bo     = (const float*)d_in[7];
    const float* W1     = (const float*)d_in[8];
    const float* b1     = (const float*)d_in[9];
    const float* W2     = (const float*)d_in[10];
    const float* b2     = (const float*)d_in[11];
    const float* ln1_g  = (const float*)d_in[12];
    const float* ln1_b  = (const float*)d_in[13];
    const float* ln2_g  = (const float*)d_in[14];
    const float* ln2_b  = (const float*)d_in[15];
    const float* lnf_g  = (const float*)d_in[16];
    const float* lnf_b  = (const float*)d_in[17];
    const float* end_w  = (const float*)d_in[18];
    const float* end_b  = (const float*)d_in[19];
    const float* head_w = (const float*)d_in[20];
    const float* head_b = (const float*)d_in[21];

    int B = out_size;   // 2048 (one sigmoid scalar per batch element)
    TorrinE0_kernel<<<B, BLOCK>>>(x, conv_w, conv_b, cls_e, Wqkv, bqkv, Wo, bo,
                                  W1, b1, W2, b2, ln1_g, ln1_b, ln2_g, ln2_b,
                                  lnf_g, lnf_b, end_w, end_b, head_w, head_b,
                                  (float*)d_out);
}

// round 3
// speedup vs baseline: 1.2298x; 1.2298x over previous
#include <cuda_runtime.h>

#define Dm 16
#define Hh 8
#define Ll 8
#define Kk 35
#define Sq 101
#define RS 20          // padded row stride (floats) for k/v rows in smem (80B, 16B-aligned)
#define BLOCK 128

// shared-weight buffer offsets (floats) — all 16-float-row bases are 16B aligned
#define OWQKV 0        // 768
#define OBQKV 768      // 48
#define OWO   816      // 256
#define OBO   1072     // 16
#define OW1   1088     // 256
#define OB1   1344     // 16
#define OW2   1360     // 256
#define OB2   1616     // 16
#define OG1   1632
#define OBE1  1648
#define OG2   1664
#define OBE2  1680
#define WTOT  1696

typedef unsigned long long u64;

__device__ __forceinline__ u64 pk2(float lo, float hi) {
    u64 r; asm("mov.b64 %0, {%1, %2};" : "=l"(r) : "f"(lo), "f"(hi)); return r;
}
__device__ __forceinline__ void upk2(u64 v, float& lo, float& hi) {
    asm("mov.b64 {%0, %1}, %2;" : "=f"(lo), "=f"(hi) : "l"(v));
}
__device__ __forceinline__ u64 fma2_(u64 a, u64 b, u64 c) {
    u64 d; asm("fma.rn.f32x2 %0, %1, %2, %3;" : "=l"(d) : "l"(a), "l"(b), "l"(c)); return d;
}
__device__ __forceinline__ u64 mul2_(u64 a, u64 b) {
    u64 d; asm("mul.rn.f32x2 %0, %1, %2;" : "=l"(d) : "l"(a), "l"(b)); return d;
}
__device__ __forceinline__ u64 add2_(u64 a, u64 b) {
    u64 d; asm("add.rn.f32x2 %0, %1, %2;" : "=l"(d) : "l"(a), "l"(b)); return d;
}
__device__ __forceinline__ float ex2_(float x) {
    float e; asm("ex2.approx.f32 %0, %1;" : "=f"(e) : "f"(x)); return e;
}

// dot of packed 16-vector a2[8] with a 16-float smem row (16B aligned)
__device__ __forceinline__ float dot16p(const u64* a2, const float* w) {
    const ulonglong2* w2 = reinterpret_cast<const ulonglong2*>(w);
    ulonglong2 p0 = w2[0], p1 = w2[1], p2 = w2[2], p3 = w2[3];
    u64 acc = mul2_(a2[0], p0.x);
    acc = fma2_(a2[1], p0.y, acc);
    acc = fma2_(a2[2], p1.x, acc);
    acc = fma2_(a2[3], p1.y, acc);
    acc = fma2_(a2[4], p2.x, acc);
    acc = fma2_(a2[5], p2.y, acc);
    acc = fma2_(a2[6], p3.x, acc);
    acc = fma2_(a2[7], p3.y, acc);
    float lo, hi; upk2(acc, lo, hi);
    return lo + hi;
}

// layernorm over packed 16-vector in-place: io = LN(in) * g + b
__device__ __forceinline__ void ln16p(u64* io, const float* g, const float* b) {
    u64 s2 = io[0];
    #pragma unroll
    for (int i = 1; i < 8; i++) s2 = add2_(s2, io[i]);
    float slo, shi; upk2(s2, slo, shi);
    float mu = (slo + shi) * (1.f / 16.f);
    u64 nm2 = pk2(-mu, -mu);
    u64 c[8];
    #pragma unroll
    for (int i = 0; i < 8; i++) c[i] = add2_(io[i], nm2);
    u64 v2 = mul2_(c[0], c[0]);
    #pragma unroll
    for (int i = 1; i < 8; i++) v2 = fma2_(c[i], c[i], v2);
    float vlo, vhi; upk2(v2, vlo, vhi);
    float inv = rsqrtf((vlo + vhi) * (1.f / 16.f) + 1e-5f);
    u64 inv2 = pk2(inv, inv);
    const ulonglong2* g2 = reinterpret_cast<const ulonglong2*>(g);
    const ulonglong2* b2 = reinterpret_cast<const ulonglong2*>(b);
    #pragma unroll
    for (int j = 0; j < 4; j++) {
        ulonglong2 gg = g2[j], bb = b2[j];
        io[2*j]   = fma2_(mul2_(c[2*j],   inv2), gg.x, bb.x);
        io[2*j+1] = fma2_(mul2_(c[2*j+1], inv2), gg.y, bb.y);
    }
}

__global__ __launch_bounds__(BLOCK, 6) void TorrinE0_kernel(
    const float* __restrict__ x,
    const float* __restrict__ conv_w,
    const float* __restrict__ conv_b,
    const float* __restrict__ cls_emb,
    const float* __restrict__ Wqkv,
    const float* __restrict__ bqkv,
    const float* __restrict__ Wo,
    const float* __restrict__ bo,
    const float* __restrict__ W1,
    const float* __restrict__ b1,
    const float* __restrict__ W2,
    const float* __restrict__ b2,
    const float* __restrict__ ln1_g, const float* __restrict__ ln1_b,
    const float* __restrict__ ln2_g, const float* __restrict__ ln2_b,
    const float* __restrict__ lnf_g, const float* __restrict__ lnf_b,
    const float* __restrict__ end_w, const float* __restrict__ end_b,
    const float* __restrict__ head_w, const float* __restrict__ head_b,
    float* __restrict__ out)
{
    // k rows [0 .. Sq*RS), v rows [Sq*RS .. 2*Sq*RS)
    // aliased as x-row staging (3500 floats <= 4040) before the layer loop.
    __shared__ __align__(16) float skv[2 * Sq * RS];
    __shared__ __align__(16) float sw[WTOT];
    __shared__ float sred[4];
    __shared__ float scls[16];

    const int b   = blockIdx.x;
    const int tid = threadIdx.x;
    const bool tok = (tid <= 100);

    // ---- stage x row + conv weights ----
    const float* xr = x + (size_t)b * 3500;
    for (int i = tid; i < 875; i += BLOCK)
        ((float4*)skv)[i] = ((const float4*)xr)[i];
    for (int i = tid; i < 140; i += BLOCK)
        ((float4*)sw)[i] = ((const float4*)conv_w)[i];
    if (tid < 16) sw[560 + tid] = conv_b[tid];
    __syncthreads();

    // ---- conv patchify -> packed h in registers ----
    u64 h2[8];
    if (tid == 0) {
        #pragma unroll
        for (int i = 0; i < 8; i++) h2[i] = pk2(cls_emb[2*i], cls_emb[2*i+1]);
    } else if (tok) {
        const float* ps = &skv[(tid - 1) * Kk];
        #pragma unroll
        for (int i = 0; i < 8; i++) {
            float a0 = sw[560 + 2*i], a1 = sw[560 + 2*i + 1];
            for (int k = 0; k < Kk; k++) {
                float p = ps[k];
                a0 += p * sw[(2*i) * Kk + k];
                a1 += p * sw[(2*i+1) * Kk + k];
            }
            h2[i] = pk2(a0, a1);
        }
    }
    __syncthreads();   // conv reads done before overwrite

    // q scale folded with log2(e) so scores are in log2 domain for ex2
    const float QS = 0.70710678118654752f * 1.44269504088896340f;

    #pragma unroll 1
    for (int l = 0; l < Ll; l++) {
        // ---- stage layer weights (vectorized) ----
        for (int i = tid; i < 192; i += BLOCK)
            ((float4*)&sw[OWQKV])[i] = ((const float4*)(Wqkv + l*768))[i];
        for (int i = tid; i < 64; i += BLOCK) {
            ((float4*)&sw[OWO])[i] = ((const float4*)(Wo + l*256))[i];
            ((float4*)&sw[OW1])[i] = ((const float4*)(W1 + l*256))[i];
            ((float4*)&sw[OW2])[i] = ((const float4*)(W2 + l*256))[i];
        }
        if (tid < 48) sw[OBQKV + tid] = bqkv[l*48 + tid];
        if (tid < 16) {
            sw[OBO  + tid] = bo[l*16 + tid];
            sw[OB1  + tid] = b1[l*16 + tid];
            sw[OB2  + tid] = b2[l*16 + tid];
            sw[OG1  + tid] = ln1_g[l*16 + tid];
            sw[OBE1 + tid] = ln1_b[l*16 + tid];
            sw[OG2  + tid] = ln2_g[l*16 + tid];
            sw[OBE2 + tid] = ln2_b[l*16 + tid];
        }
        __syncthreads();

        // ---- qkv projection: q stays in registers (pre-scaled), k/v -> smem ----
        u64 qr2[8];
        if (tok) {
            u64* krow = (u64*)&skv[tid * RS];
            u64* vrow = (u64*)&skv[Sq * RS + tid * RS];
            #pragma unroll
            for (int e2 = 0; e2 < 8; e2++) {
                float q0 = sw[OBQKV + 2*e2]     + dot16p(h2, &sw[OWQKV + (2*e2)*16]);
                float q1 = sw[OBQKV + 2*e2 + 1] + dot16p(h2, &sw[OWQKV + (2*e2+1)*16]);
                qr2[e2] = pk2(q0 * QS, q1 * QS);
                float k0 = sw[OBQKV + 16 + 2*e2]     + dot16p(h2, &sw[OWQKV + (16 + 2*e2)*16]);
                float k1 = sw[OBQKV + 16 + 2*e2 + 1] + dot16p(h2, &sw[OWQKV + (17 + 2*e2)*16]);
                krow[e2] = pk2(k0, k1);
                float v0 = sw[OBQKV + 32 + 2*e2]     + dot16p(h2, &sw[OWQKV + (32 + 2*e2)*16]);
                float v1 = sw[OBQKV + 32 + 2*e2 + 1] + dot16p(h2, &sw[OWQKV + (33 + 2*e2)*16]);
                vrow[e2] = pk2(v0, v1);
            }
        }
        __syncthreads();

        // ---- attention + out-proj + LN1 + FFN + LN2 ----
        if (tok) {
            u64 ctx2[8];
            float ssum[8];
            #pragma unroll
            for (int i = 0; i < 8; i++) { ctx2[i] = 0ULL; ssum[i] = 0.f; }

            #pragma unroll 2
            for (int t = 0; t < Sq; t++) {
                const ulonglong2* kr = (const ulonglong2*)&skv[t * RS];
                const ulonglong2* vr = (const ulonglong2*)&skv[Sq * RS + t * RS];
                #pragma unroll
                for (int j = 0; j < 4; j++) {
                    ulonglong2 kj = kr[j];      // heads 2j, 2j+1 (k pairs)
                    ulonglong2 vj = vr[j];      // heads 2j, 2j+1 (v pairs)
                    {
                        u64 d2 = mul2_(qr2[2*j], kj.x);
                        float dlo, dhi; upk2(d2, dlo, dhi);
                        float e = ex2_(dlo + dhi);
                        ssum[2*j] += e;
                        ctx2[2*j] = fma2_(pk2(e, e), vj.x, ctx2[2*j]);
                    }
                    {
                        u64 d2 = mul2_(qr2[2*j+1], kj.y);
                        float dlo, dhi; upk2(d2, dlo, dhi);
                        float e = ex2_(dlo + dhi);
                        ssum[2*j+1] += e;
                        ctx2[2*j+1] = fma2_(pk2(e, e), vj.y, ctx2[2*j+1]);
                    }
                }
            }
            #pragma unroll
            for (int i = 0; i < 8; i++) {
                float r = __fdividef(1.f, ssum[i]);
                ctx2[i] = mul2_(ctx2[i], pk2(r, r));
            }

            // out projection + residual + LN1
            u64 nh2[8];
            #pragma unroll
            for (int o2 = 0; o2 < 8; o2++) {
                float d0 = sw[OBO + 2*o2]     + dot16p(ctx2, &sw[OWO + (2*o2)*16]);
                float d1 = sw[OBO + 2*o2 + 1] + dot16p(ctx2, &sw[OWO + (2*o2+1)*16]);
                nh2[o2] = add2_(h2[o2], pk2(d0, d1));
            }
            ln16p(nh2, &sw[OG1], &sw[OBE1]);
            #pragma unroll
            for (int i = 0; i < 8; i++) h2[i] = nh2[i];

            // FFN
            u64 ff2[8];
            #pragma unroll
            for (int f2 = 0; f2 < 8; f2++) {
                float f0 = fmaxf(sw[OB1 + 2*f2]     + dot16p(h2, &sw[OW1 + (2*f2)*16]),   0.f);
                float f1 = fmaxf(sw[OB1 + 2*f2 + 1] + dot16p(h2, &sw[OW1 + (2*f2+1)*16]), 0.f);
                ff2[f2] = pk2(f0, f1);
            }
            #pragma unroll
            for (int o2 = 0; o2 < 8; o2++) {
                float d0 = sw[OB2 + 2*o2]     + dot16p(ff2, &sw[OW2 + (2*o2)*16]);
                float d1 = sw[OB2 + 2*o2 + 1] + dot16p(ff2, &sw[OW2 + (2*o2+1)*16]);
                nh2[o2] = add2_(h2[o2], pk2(d0, d1));
            }
            ln16p(nh2, &sw[OG2], &sw[OBE2]);
            #pragma unroll
            for (int i = 0; i < 8; i++) h2[i] = nh2[i];
        }
        __syncthreads();   // all reads of skv/sw done before next layer overwrites
    }

    // ---- final LN on CLS token + head ----
    if (tid == 0) {
        float hv[16];
        #pragma unroll
        for (int i = 0; i < 8; i++) upk2(h2[i], hv[2*i], hv[2*i+1]);
        float mu = 0.f;
        #pragma unroll
        for (int d = 0; d < 16; d++) mu += hv[d];
        mu *= (1.f/16.f);
        float var = 0.f;
        #pragma unroll
        for (int d = 0; d < 16; d++) { float c = hv[d] - mu; var += c*c; }
        var *= (1.f/16.f);
        float inv = rsqrtf(var + 1e-5f);
        #pragma unroll
        for (int d = 0; d < 16; d++)
            scls[d] = (hv[d] - mu) * inv * lnf_g[d] + lnf_b[d];
    }
    __syncthreads();

    float part = 0.f;
    if (tid < 100) {
        u64 c2[8];
        #pragma unroll
        for (int i = 0; i < 8; i++) c2[i] = pk2(scls[2*i], scls[2*i+1]);
        float acc = end_b[tid] + dot16p(c2, (const float*)0 + 0 == 0 ? (const float*)(end_w + tid*16) : 0);
        part = acc * head_w[tid];
    }
    #pragma unroll
    for (int off = 16; off > 0; off >>= 1)
        part += __shfl_down_sync(0xffffffffu, part, off);
    if ((tid & 31) == 0) sred[tid >> 5] = part;
    __syncthreads();
    if (tid == 0) {
        float z = sred[0] + sred[1] + sred[2] + sred[3] + head_b[0];
        out[b] = 1.f / (1.f + ex2_(-z * 1.44269504088896340f));
    }
}

extern "C" void kernel_launch(void* const* d_in, const int* in_sizes, int n_in,
                              void* d_out, int out_size) {
    const float* x      = (const float*)d_in[0];
    const float* conv_w = (const float*)d_in[1];
    const float* conv_b = (const float*)d_in[2];
    const float* cls_e  = (const float*)d_in[3];
    const float* Wqkv   = (const float*)d_in[4];
    const float* bqkv   = (const float*)d_in[5];
    const float* Wo     = (const float*)d_in[6];
    const float* bo     = (const float*)d_in[7];
    const float* W1     = (const float*)d_in[8];
    const float* b1     = (const float*)d_in[9];
    const float* W2     = (const float*)d_in[10];
    const float* b2     = (const float*)d_in[11];
    const float* ln1_g  = (const float*)d_in[12];
    const float* ln1_b  = (const float*)d_in[13];
    const float* ln2_g  = (const float*)d_in[14];
    const float* ln2_b  = (const float*)d_in[15];
    const float* lnf_g  = (const float*)d_in[16];
    const float* lnf_b  = (const float*)d_in[17];
    const float* end_w  = (const float*)d_in[18];
    const float* end_b  = (const float*)d_in[19];
    const float* head_w = (const float*)d_in[20];
    const float* head_b = (const float*)d_in[21];

    int B = out_size;   // 2048
    TorrinE0_kernel<<<B, BLOCK>>>(x, conv_w, conv_b, cls_e, Wqkv, bqkv, Wo, bo,
                                  W1, b1, W2, b2, ln1_g, ln1_b, ln2_g, ln2_b,
                                  lnf_g, lnf_b, end_w, end_b, head_w, head_b,
                                  (float*)d_out);
}

// round 4
// speedup vs baseline: 1.2553x; 1.0208x over previous
#include <cuda_runtime.h>

#define Ll 8
#define Kk 35
#define Sq 101
#define NP 51          // key pairs (50 full + 1 with zero pad)
#define PRS 36         // floats per pair row (32 used + 4 pad) -> 144B, 16B aligned
#define BLOCK 128

#define KOFF 0
#define VOFF (NP * PRS)            // 1836
#define SKVTOT (2 * NP * PRS)      // 3672 floats (also aliases x staging, 3500)

// shared-weight buffer offsets (floats) — all 16-float rows 16B aligned
#define OWQKV 0
#define OBQKV 768
#define OWO   816
#define OBO   1072
#define OW1   1088
#define OB1   1344
#define OW2   1360
#define OB2   1616
#define OG1   1632
#define OBE1  1648
#define OG2   1664
#define OBE2  1680
#define WTOT  1696

typedef unsigned long long u64;

__device__ __forceinline__ u64 pk2(float lo, float hi) {
    u64 r; asm("mov.b64 %0, {%1, %2};" : "=l"(r) : "f"(lo), "f"(hi)); return r;
}
__device__ __forceinline__ void upk2(u64 v, float& lo, float& hi) {
    asm("mov.b64 {%0, %1}, %2;" : "=f"(lo), "=f"(hi) : "l"(v));
}
__device__ __forceinline__ u64 fma2_(u64 a, u64 b, u64 c) {
    u64 d; asm("fma.rn.f32x2 %0, %1, %2, %3;" : "=l"(d) : "l"(a), "l"(b), "l"(c)); return d;
}
__device__ __forceinline__ u64 mul2_(u64 a, u64 b) {
    u64 d; asm("mul.rn.f32x2 %0, %1, %2;" : "=l"(d) : "l"(a), "l"(b)); return d;
}
__device__ __forceinline__ u64 add2_(u64 a, u64 b) {
    u64 d; asm("add.rn.f32x2 %0, %1, %2;" : "=l"(d) : "l"(a), "l"(b)); return d;
}
__device__ __forceinline__ float ex2_(float x) {
    float e; asm("ex2.approx.f32 %0, %1;" : "=f"(e) : "f"(x)); return e;
}

// dot of packed 16-vector a2[8] with a 16-float 16B-aligned row
__device__ __forceinline__ float dot16p(const u64* a2, const float* w) {
    const ulonglong2* w2 = reinterpret_cast<const ulonglong2*>(w);
    ulonglong2 p0 = w2[0], p1 = w2[1], p2 = w2[2], p3 = w2[3];
    u64 acc = mul2_(a2[0], p0.x);
    acc = fma2_(a2[1], p0.y, acc);
    acc = fma2_(a2[2], p1.x, acc);
    acc = fma2_(a2[3], p1.y, acc);
    acc = fma2_(a2[4], p2.x, acc);
    acc = fma2_(a2[5], p2.y, acc);
    acc = fma2_(a2[6], p3.x, acc);
    acc = fma2_(a2[7], p3.y, acc);
    float lo, hi; upk2(acc, lo, hi);
    return lo + hi;
}

__device__ __forceinline__ void ln16p(u64* io, const float* g, const float* b) {
    u64 s2 = io[0];
    #pragma unroll
    for (int i = 1; i < 8; i++) s2 = add2_(s2, io[i]);
    float slo, shi; upk2(s2, slo, shi);
    float mu = (slo + shi) * (1.f / 16.f);
    u64 nm2 = pk2(-mu, -mu);
    u64 c[8];
    #pragma unroll
    for (int i = 0; i < 8; i++) c[i] = add2_(io[i], nm2);
    u64 v2 = mul2_(c[0], c[0]);
    #pragma unroll
    for (int i = 1; i < 8; i++) v2 = fma2_(c[i], c[i], v2);
    float vlo, vhi; upk2(v2, vlo, vhi);
    float inv = rsqrtf((vlo + vhi) * (1.f / 16.f) + 1e-5f);
    u64 inv2 = pk2(inv, inv);
    const ulonglong2* g2 = reinterpret_cast<const ulonglong2*>(g);
    const ulonglong2* b2 = reinterpret_cast<const ulonglong2*>(b);
    #pragma unroll
    for (int j = 0; j < 4; j++) {
        ulonglong2 gg = g2[j], bb = b2[j];
        io[2*j]   = fma2_(mul2_(c[2*j],   inv2), gg.x, bb.x);
        io[2*j+1] = fma2_(mul2_(c[2*j+1], inv2), gg.y, bb.y);
    }
}

__global__ __launch_bounds__(BLOCK, 5) void TorrinE0_kernel(
    const float* __restrict__ x,
    const float* __restrict__ conv_w,
    const float* __restrict__ conv_b,
    const float* __restrict__ cls_emb,
    const float* __restrict__ Wqkv,
    const float* __restrict__ bqkv,
    const float* __restrict__ Wo,
    const float* __restrict__ bo,
    const float* __restrict__ W1,
    const float* __restrict__ b1,
    const float* __restrict__ W2,
    const float* __restrict__ b2,
    const float* __restrict__ ln1_g, const float* __restrict__ ln1_b,
    const float* __restrict__ ln2_g, const float* __restrict__ ln2_b,
    const float* __restrict__ lnf_g, const float* __restrict__ lnf_b,
    const float* __restrict__ end_w, const float* __restrict__ end_b,
    const float* __restrict__ head_w, const float* __restrict__ head_b,
    float* __restrict__ out)
{
    __shared__ __align__(16) float skv[SKVTOT];      // kT | vT (aliases x staging)
    __shared__ __align__(16) float sw[WTOT];
    __shared__ __align__(16) u64 shh[102 * 9];       // h2 stash, stride 9 u64 (bank spread)
    __shared__ float sred[4];
    __shared__ float scls[16];

    const int b   = blockIdx.x;
    const int tid = threadIdx.x;
    const bool tok = (tid <= 100);

    // ---- stage x row + conv weights ----
    const float* xr = x + (size_t)b * 3500;
    for (int i = tid; i < 875; i += BLOCK)
        ((float4*)skv)[i] = ((const float4*)xr)[i];
    for (int i = tid; i < 140; i += BLOCK)
        ((float4*)sw)[i] = ((const float4*)conv_w)[i];
    if (tid < 16) sw[560 + tid] = conv_b[tid];
    __syncthreads();

    // ---- conv patchify -> packed h in registers ----
    u64 h2[8];
    if (tid == 0) {
        #pragma unroll
        for (int i = 0; i < 8; i++) h2[i] = pk2(cls_emb[2*i], cls_emb[2*i+1]);
    } else if (tok) {
        const float* ps = &skv[(tid - 1) * Kk];
        #pragma unroll
        for (int i = 0; i < 8; i++) {
            float a0 = sw[560 + 2*i], a1 = sw[560 + 2*i + 1];
            for (int k = 0; k < Kk; k++) {
                float p = ps[k];
                a0 += p * sw[(2*i) * Kk + k];
                a1 += p * sw[(2*i+1) * Kk + k];
            }
            h2[i] = pk2(a0, a1);
        }
    }
    __syncthreads();   // conv reads done before k/v overwrite

    const float QS = 0.70710678118654752f * 1.44269504088896340f;  // scale * log2(e)
    const int wbase = (tid >> 1) * PRS + (tid & 1);   // col parity = key parity

    #pragma unroll 1
    for (int l = 0; l < Ll; l++) {
        // ---- stage layer weights ----
        for (int i = tid; i < 192; i += BLOCK)
            ((float4*)&sw[OWQKV])[i] = ((const float4*)(Wqkv + l*768))[i];
        for (int i = tid; i < 64; i += BLOCK) {
            ((float4*)&sw[OWO])[i] = ((const float4*)(Wo + l*256))[i];
            ((float4*)&sw[OW1])[i] = ((const float4*)(W1 + l*256))[i];
            ((float4*)&sw[OW2])[i] = ((const float4*)(W2 + l*256))[i];
        }
        if (tid < 48) sw[OBQKV + tid] = bqkv[l*48 + tid];
        if (tid < 16) {
            sw[OBO  + tid] = bo[l*16 + tid];
            sw[OB1  + tid] = b1[l*16 + tid];
            sw[OB2  + tid] = b2[l*16 + tid];
            sw[OG1  + tid] = ln1_g[l*16 + tid];
            sw[OBE1 + tid] = ln1_b[l*16 + tid];
            sw[OG2  + tid] = ln2_g[l*16 + tid];
            sw[OBE2 + tid] = ln2_b[l*16 + tid];
        }
        __syncthreads();

        // ---- qkv projection: q in regs (broadcast-packed, pre-scaled), k/v transposed to smem ----
        u64 qb0[8];        // (q0,q0) per head, scaled
        float q1s[8];      // q1 per head, scaled
        if (tok) {
            #pragma unroll
            for (int h = 0; h < 8; h++) {
                float q0 = sw[OBQKV + 2*h]     + dot16p(h2, &sw[OWQKV + (2*h)*16]);
                float q1 = sw[OBQKV + 2*h + 1] + dot16p(h2, &sw[OWQKV + (2*h+1)*16]);
                q0 *= QS; q1 *= QS;
                qb0[h] = pk2(q0, q0);
                q1s[h] = q1;
                float k0 = sw[OBQKV + 16 + 2*h]     + dot16p(h2, &sw[OWQKV + (16 + 2*h)*16]);
                float k1 = sw[OBQKV + 16 + 2*h + 1] + dot16p(h2, &sw[OWQKV + (17 + 2*h)*16]);
                skv[KOFF + wbase + 4*h]     = k0;
                skv[KOFF + wbase + 4*h + 2] = k1;
                float v0 = sw[OBQKV + 32 + 2*h]     + dot16p(h2, &sw[OWQKV + (32 + 2*h)*16]);
                float v1 = sw[OBQKV + 32 + 2*h + 1] + dot16p(h2, &sw[OWQKV + (33 + 2*h)*16]);
                skv[VOFF + wbase + 4*h]     = v0;
                skv[VOFF + wbase + 4*h + 2] = v1;
            }
        } else if (tid == 101) {
            // zero-pad the odd slot of pair 50: exp(0)=1 handled by -1 correction; v=0
            #pragma unroll
            for (int h = 0; h < 8; h++) {
                skv[KOFF + wbase + 4*h]     = 0.f;
                skv[KOFF + wbase + 4*h + 2] = 0.f;
                skv[VOFF + wbase + 4*h]     = 0.f;
                skv[VOFF + wbase + 4*h + 2] = 0.f;
            }
        }
        __syncthreads();

        // ---- attention over 51 key-pairs ----
        if (tok) {
            // stash h2 to smem to free registers across the hot loop
            u64* st = &shh[tid * 9];
            #pragma unroll
            for (int i = 0; i < 8; i++) st[i] = h2[i];

            u64 ssum2[8], ctx0[8], ctx1[8];
            #pragma unroll
            for (int i = 0; i < 8; i++) { ssum2[i] = 0ULL; ctx0[i] = 0ULL; ctx1[i] = 0ULL; }

            const ulonglong2* kpp = (const ulonglong2*)&skv[KOFF];
            const ulonglong2* vpp = (const ulonglong2*)&skv[VOFF];
            #pragma unroll 1
            for (int p = 0; p < NP; p++) {
                #pragma unroll
                for (int h = 0; h < 8; h++) {
                    ulonglong2 kk = kpp[h];            // (k0e,k0o),(k1e,k1o)
                    u64 d2 = mul2_(qb0[h], kk.x);      // (q0*k0e, q0*k0o)
                    float k1e, k1o; upk2(kk.y, k1e, k1o);
                    float se, so;   upk2(d2, se, so);
                    se = fmaf(q1s[h], k1e, se);
                    so = fmaf(q1s[h], k1o, so);
                    float ee = ex2_(se), eo = ex2_(so);
                    u64 ep = pk2(ee, eo);
                    ssum2[h] = add2_(ssum2[h], ep);
                    ulonglong2 vv = vpp[h];            // (v0e,v0o),(v1e,v1o)
                    ctx0[h] = fma2_(ep, vv.x, ctx0[h]);
                    ctx1[h] = fma2_(ep, vv.y, ctx1[h]);
                }
                kpp += 9; vpp += 9;
            }

            // finalize softmax (subtract pad's exp(0)=1 from the odd-sum half)
            u64 ctxp[8];
            #pragma unroll
            for (int h = 0; h < 8; h++) {
                float slo, shi; upk2(ssum2[h], slo, shi);
                float r = __fdividef(1.f, slo + shi - 1.f);
                float a0, a1, b0, b1v;
                upk2(ctx0[h], a0, a1);
                upk2(ctx1[h], b0, b1v);
                ctxp[h] = pk2((a0 + a1) * r, (b0 + b1v) * r);
            }

            // reload h2
            #pragma unroll
            for (int i = 0; i < 8; i++) h2[i] = st[i];

            // out projection + residual + LN1
            u64 nh2[8];
            #pragma unroll
            for (int o = 0; o < 8; o++) {
                float d0 = sw[OBO + 2*o]     + dot16p(ctxp, &sw[OWO + (2*o)*16]);
                float d1 = sw[OBO + 2*o + 1] + dot16p(ctxp, &sw[OWO + (2*o+1)*16]);
                nh2[o] = add2_(h2[o], pk2(d0, d1));
            }
            ln16p(nh2, &sw[OG1], &sw[OBE1]);
            #pragma unroll
            for (int i = 0; i < 8; i++) h2[i] = nh2[i];

            // FFN
            u64 ff2[8];
            #pragma unroll
            for (int f = 0; f < 8; f++) {
                float f0 = fmaxf(sw[OB1 + 2*f]     + dot16p(h2, &sw[OW1 + (2*f)*16]),   0.f);
                float f1 = fmaxf(sw[OB1 + 2*f + 1] + dot16p(h2, &sw[OW1 + (2*f+1)*16]), 0.f);
                ff2[f] = pk2(f0, f1);
            }
            #pragma unroll
            for (int o = 0; o < 8; o++) {
                float d0 = sw[OB2 + 2*o]     + dot16p(ff2, &sw[OW2 + (2*o)*16]);
                float d1 = sw[OB2 + 2*o + 1] + dot16p(ff2, &sw[OW2 + (2*o+1)*16]);
                nh2[o] = add2_(h2[o], pk2(d0, d1));
            }
            ln16p(nh2, &sw[OG2], &sw[OBE2]);
            #pragma unroll
            for (int i = 0; i < 8; i++) h2[i] = nh2[i];
        }
        __syncthreads();   // all reads of skv/sw done before next layer overwrites
    }

    // ---- final LN on CLS token + head ----
    if (tid == 0) {
        float hv[16];
        #pragma unroll
        for (int i = 0; i < 8; i++) upk2(h2[i], hv[2*i], hv[2*i+1]);
        float mu = 0.f;
        #pragma unroll
        for (int d = 0; d < 16; d++) mu += hv[d];
        mu *= (1.f/16.f);
        float var = 0.f;
        #pragma unroll
        for (int d = 0; d < 16; d++) { float c = hv[d] - mu; var += c*c; }
        var *= (1.f/16.f);
        float inv = rsqrtf(var + 1e-5f);
        #pragma unroll
        for (int d = 0; d < 16; d++)
            scls[d] = (hv[d] - mu) * inv * lnf_g[d] + lnf_b[d];
    }
    __syncthreads();

    float part = 0.f;
    if (tid < 100) {
        u64 c2[8];
        #pragma unroll
        for (int i = 0; i < 8; i++) c2[i] = pk2(scls[2*i], scls[2*i+1]);
        float acc = end_b[tid] + dot16p(c2, end_w + tid * 16);
        part = acc * head_w[tid];
    }
    #pragma unroll
    for (int off = 16; off > 0; off >>= 1)
        part += __shfl_down_sync(0xffffffffu, part, off);
    if ((tid & 31) == 0) sred[tid >> 5] = part;
    __syncthreads();
    if (tid == 0) {
        float z = sred[0] + sred[1] + sred[2] + sred[3] + head_b[0];
        out[b] = 1.f / (1.f + ex2_(-z * 1.44269504088896340f));
    }
}

extern "C" void kernel_launch(void* const* d_in, const int* in_sizes, int n_in,
                              void* d_out, int out_size) {
    const float* x      = (const float*)d_in[0];
    const float* conv_w = (const float*)d_in[1];
    const float* conv_b = (const float*)d_in[2];
    const float* cls_e  = (const float*)d_in[3];
    const float* Wqkv   = (const float*)d_in[4];
    const float* bqkv   = (const float*)d_in[5];
    const float* Wo     = (const float*)d_in[6];
    const float* bo     = (const float*)d_in[7];
    const float* W1     = (const float*)d_in[8];
    const float* b1     = (const float*)d_in[9];
    const float* W2     = (const float*)d_in[10];
    const float* b2     = (const float*)d_in[11];
    const float* ln1_g  = (const float*)d_in[12];
    const float* ln1_b  = (const float*)d_in[13];
    const float* ln2_g  = (const float*)d_in[14];
    const float* ln2_b  = (const float*)d_in[15];
    const float* lnf_g  = (const float*)d_in[16];
    const float* lnf_b  = (const float*)d_in[17];
    const float* end_w  = (const float*)d_in[18];
    const float* end_b  = (const float*)d_in[19];
    const float* head_w = (const float*)d_in[20];
    const float* head_b = (const float*)d_in[21];

    int B = out_size;   // 2048
    TorrinE0_kernel<<<B, BLOCK>>>(x, conv_w, conv_b, cls_e, Wqkv, bqkv, Wo, bo,
                                  W1, b1, W2, b2, ln1_g, ln1_b, ln2_g, ln2_b,
                                  lnf_g, lnf_b, end_w, end_b, head_w, head_b,
                                  (float*)d_out);
}